// round 3
// baseline (speedup 1.0000x reference)
#include <cuda_runtime.h>
#include <math.h>

#define EPSF 1e-4f
typedef unsigned long long u64;

__device__ __forceinline__ u64 pack2(float x){
  u64 r; unsigned xi = __float_as_uint(x);
  asm("mov.b64 %0, {%1, %1};" : "=l"(r) : "r"(xi));
  return r;
}
__device__ __forceinline__ void fma2(u64 &acc, u64 a, u64 b){
  asm("fma.rn.f32x2 %0, %1, %2, %0;" : "+l"(acc) : "l"(a), "l"(b));
}
__device__ __forceinline__ float2 unpack2(u64 v){
  unsigned lo, hi;
  asm("mov.b64 {%0, %1}, %2;" : "=r"(lo), "=r"(hi) : "l"(v));
  return make_float2(__uint_as_float(lo), __uint_as_float(hi));
}
__device__ __forceinline__ float rsum32(float v){
  #pragma unroll
  for (int o=16;o;o>>=1) v += __shfl_xor_sync(0xffffffffu, v, o);
  return v;
}
__device__ __forceinline__ float rsum16(float v){
  #pragma unroll
  for (int o=8;o;o>>=1) v += __shfl_xor_sync(0xffffffffu, v, o);
  return v;
}
__device__ __forceinline__ float rmax16(float v){
  #pragma unroll
  for (int o=8;o;o>>=1) v = fmaxf(v, __shfl_xor_sync(0xffffffffu, v, o));
  return v;
}
__device__ __forceinline__ float sigm(float x){ return 1.f/(1.f+expf(-x)); }
__device__ __forceinline__ float splus(float x){ return fmaxf(x,0.f)+log1pf(expf(-fabsf(x))); }

__global__ void __launch_bounds__(256,1) cfrm_kernel(
   const int* __restrict__ tokens, const float* __restrict__ emb,
   const float* __restrict__ ln_g, const float* __restrict__ ln_b,
   const float* __restrict__ w1, const float* __restrict__ b1,
   const float* __restrict__ w2, const float* __restrict__ b2,
   const float* __restrict__ gate_w, const float* __restrict__ gate_b,
   const float* __restrict__ assign_w, const float* __restrict__ assign_b,
   const float* __restrict__ nov_w, const float* __restrict__ nov_b,
   const float* __restrict__ relax_w, const float* __restrict__ relax_b,
   const float* __restrict__ cc_w, const float* __restrict__ cc_b,
   const float* __restrict__ cs_w, const float* __restrict__ cs_b,
   const float* __restrict__ md_w, const float* __restrict__ md_b,
   const float* __restrict__ att_w, const float* __restrict__ att_b,
   const float* __restrict__ cw1, const float* __restrict__ cb1,
   const float* __restrict__ cw2, const float* __restrict__ cb2,
   float* __restrict__ out)
{
  __shared__ __align__(16) float sc[2][16][132];
  __shared__ __align__(16) float smix[2][16][16];
  __shared__ __align__(16) float sci[2][260];
  __shared__ __align__(8)  float sct2[128][2];
  __shared__ __align__(16) float sh1[2][128];
  __shared__ __align__(16) float satt[2][128];
  __shared__ __align__(16) float4 sbuf[2][4][32];
  __shared__ float ssp[2][16], sma[2][16], sal[2][16], sgs[2][16];
  __shared__ float ssq[2][16], sms[2][16], smm[2][16];
  __shared__ float sraw[2][4][16];
  __shared__ float sred[2][4][3];
  __shared__ float snv[2], srl[2];
  __shared__ int sidx[2];

  const int tid  = threadIdx.x;
  const int g    = tid >> 7;
  const int ht   = tid & 127;
  const int lane = tid & 31;
  const int wg   = (tid >> 5) & 3;
  const int b    = blockIdx.x * 2 + g;

  for (int i = tid; i < 2*16*132; i += 256) ((float*)sc)[i] = 0.f;
  if (tid < 32){ ((float*)ssp)[tid] = 1.f; ((float*)sma)[tid] = 0.f; }
  __syncthreads();

  const int cA  = (tid >> 5) * 2;   // two clusters owned per warp (cc head)
  const int h4  = lane;             // float4 chunk of h owned
  const int j4  = ht & 31;          // matvec output chunk
  const int isl = ht >> 5;          // matvec reduction slice

  for (int t = 0; t < 512; t++){
    const int tok = tokens[b*512 + t];
    const float valid = (tok != 0) ? 1.f : 0.f;
    const float e = emb[tok*128 + ht];
    {
      float ps = rsum32(e);
      float pq = rsum32(e*e);
      if (lane == 0){ sred[g][wg][0] = ps; sred[g][wg][1] = pq; }
    }
    if (ht < 32){
      const bool ok = lane < 16;
      float sp = ok ? ssp[g][lane] : 0.f;
      float m  = ok ? sma[g][lane] : 0.f;
      float score = ok ? m + logf(1.f/(sp+EPSF)+EPSF) : -3.4e38f;
      float mx = rmax16(score);
      float ex = ok ? expf(score - mx) : 0.f;
      float sm = rsum16(ex);
      float a  = ex / sm;
      if (ok) sal[g][lane] = a;
      float u   = rsum16(ok ? a*sp : 0.f);
      float ent = rsum16(ok ? -a*logf(fmaxf(a,1e-8f)) : 0.f);
      float mm2 = rmax16(ok ? m : -3.4e38f);
      float en  = mm2 + logf(rsum16(ok ? expf(m - mm2) : 0.f));
      if (lane == 0){ sci[g][256] = u; sci[g][258] = en; sci[g][259] = ent; }
    }
    __syncthreads(); // S1
    {
      float mu = (sred[g][0][0]+sred[g][1][0]+sred[g][2][0]+sred[g][3][0]) * (1.f/128.f);
      float mq = (sred[g][0][1]+sred[g][1][1]+sred[g][2][1]+sred[g][3][1]) * (1.f/128.f);
      float var = mq - mu*mu;
      float te = (e - mu) * rsqrtf(var + 1e-5f) * ln_g[ht] + ln_b[ht];
      sci[g][ht] = te;
      float core = 0.f;
      #pragma unroll
      for (int c = 0; c < 16; c++) core += sal[g][c] * sc[g][c][ht];
      sci[g][128+ht] = core;
      float dv = 0.f;
      #pragma unroll
      for (int c = 0; c < 16; c++){ float dd = sc[g][c][ht] - core; dv += sal[g][c]*dd*dd; }
      dv = rsum32(dv);
      if (lane == 0) sred[g][wg][2] = dv;
    }
    __syncthreads(); // S2
    const float dvr = (sred[g][0][2]+sred[g][1][2]+sred[g][2][2]+sred[g][3][2]) * (1.f/128.f);
    {
      u64 a0 = 0, a1 = 0;
      const int lo = isl * 64;
      #pragma unroll 4
      for (int i = lo; i < lo + 64; i++){
        u64 xp = pack2(sci[g][i]);
        ulonglong2 w = *(const ulonglong2*)&w1[i*128 + j4*4];
        fma2(a0, xp, w.x); fma2(a1, xp, w.y);
      }
      if (isl == 0){
        float ex4[4] = { sci[g][256], dvr, sci[g][258], sci[g][259] };
        #pragma unroll
        for (int k = 0; k < 4; k++){
          u64 xp = pack2(ex4[k]);
          ulonglong2 w = *(const ulonglong2*)&w1[(256+k)*128 + j4*4];
          fma2(a0, xp, w.x); fma2(a1, xp, w.y);
        }
      }
      float2 l = unpack2(a0), h2 = unpack2(a1);
      sbuf[g][isl][j4] = make_float4(l.x, l.y, h2.x, h2.y);
    }
    __syncthreads(); // S3
    {
      float s = b1[ht];
      #pragma unroll
      for (int k = 0; k < 4; k++) s += ((const float*)sbuf[g][k])[ht];
      sh1[g][ht] = tanhf(s);
    }
    __syncthreads(); // S4
    {
      u64 a0 = 0, a1 = 0;
      const int lo = isl * 32;
      #pragma unroll 4
      for (int i = lo; i < lo + 32; i++){
        u64 xp = pack2(sh1[g][i]);
        ulonglong2 w = *(const ulonglong2*)&w2[i*128 + j4*4];
        fma2(a0, xp, w.x); fma2(a1, xp, w.y);
      }
      float2 l = unpack2(a0), h2 = unpack2(a1);
      sbuf[g][isl][j4] = make_float4(l.x, l.y, h2.x, h2.y);
    }
    __syncthreads(); // S5
    {
      float s = b2[ht];
      #pragma unroll
      for (int k = 0; k < 4; k++) s += ((const float*)sbuf[g][k])[ht];
      sct2[ht][g] = tanhf(s);
    }
    __syncthreads(); // S6

    u64 acc[2][2][2];
    #pragma unroll
    for (int a=0;a<2;a++){ acc[a][0][0]=0; acc[a][0][1]=0; acc[a][1][0]=0; acc[a][1][1]=0; }
    {
      const ulonglong2* W = (const ulonglong2*)cc_w;
      const int base = cA*32 + h4;
      #pragma unroll 4
      for (int i = 0; i < 128; i++){
        float2 ct = *(const float2*)&sct2[i][0];
        u64 p0 = pack2(ct.x), p1 = pack2(ct.y);
        ulonglong2 wv0 = W[i*512 + base];
        ulonglong2 wv1 = W[i*512 + base + 32];
        fma2(acc[0][0][0], p0, wv0.x); fma2(acc[0][0][1], p0, wv0.y);
        fma2(acc[1][0][0], p1, wv0.x); fma2(acc[1][0][1], p1, wv0.y);
        fma2(acc[0][1][0], p0, wv1.x); fma2(acc[0][1][1], p0, wv1.y);
        fma2(acc[1][1][0], p1, wv1.x); fma2(acc[1][1][1], p1, wv1.y);
      }
    }
    {
      u64 a0 = 0, a1 = 0;
      const int lo = isl * 32;
      #pragma unroll 4
      for (int i = lo; i < lo + 32; i++){
        u64 xp = pack2(sct2[i][g]);
        ulonglong2 w = *(const ulonglong2*)&att_w[i*128 + j4*4];
        fma2(a0, xp, w.x); fma2(a1, xp, w.y);
      }
      float2 l = unpack2(a0), h2 = unpack2(a1);
      sbuf[g][isl][j4] = make_float4(l.x, l.y, h2.x, h2.y);
    }
    if (ht < 64){
      const int head = ht >> 4;
      const int c = ht & 15;
      const float* W  = (head==0)? gate_w : (head==1)? assign_w : (head==2)? cs_w : md_w;
      const float* Bp = (head==0)? gate_b : (head==1)? assign_b : (head==2)? cs_b : md_b;
      float s = Bp[c];
      #pragma unroll 4
      for (int i = 0; i < 128; i++) s += sct2[i][g] * W[i*16 + c];
      sraw[g][head][c] = s;
    } else if (ht < 96){
      float s = 0.f;
      #pragma unroll
      for (int k = 0; k < 4; k++){ int i = (ht-64) + k*32; s += sct2[i][g] * nov_w[i]; }
      s = rsum32(s);
      if (lane == 0) snv[g] = sigm(s + nov_b[0]) * valid;
    } else {
      float s = 0.f;
      #pragma unroll
      for (int k = 0; k < 4; k++){ int i = (ht-96) + k*32; s += sct2[i][g] * relax_w[i]; }
      s = rsum32(s);
      if (lane == 0) srl[g] = sigm(s + relax_b[0]) * valid;
    }
    __syncthreads(); // S7
    {
      float s = att_b[ht];
      #pragma unroll
      for (int k = 0; k < 4; k++) s += ((const float*)sbuf[g][k])[ht];
      satt[g][ht] = s;
    }
    if (ht < 32){
      const bool ok = lane < 16;
      float graw = ok ? sraw[g][0][lane] : 0.f;
      float araw = ok ? sraw[g][1][lane] : -3.4e38f;
      float mx = rmax16(araw);
      float ex = ok ? expf(araw - mx) : 0.f;
      float sm = rsum16(ex);
      if (ok){
        float assign = ex / sm;
        float gate = sigm(graw) * valid;
        float ss = gate * assign;
        sgs[g][lane] = ss;
        float cs = splus(sraw[g][2][lane]) + EPSF;
        float md = tanhf(sraw[g][3][lane]);
        float sp = ssp[g][lane]; sp += ss*(cs - sp); ssp[g][lane] = sp;
        float m  = sma[g][lane]; m  += ss*md;        sma[g][lane] = m;
      }
    }
    __syncthreads(); // S8
    {
      #pragma unroll
      for (int cc = 0; cc < 2; cc++){
        const int c = cA + cc;
        float4 bv = *(const float4*)&cc_b[c*128 + h4*4];
        #pragma unroll
        for (int gg = 0; gg < 2; gg++){
          float2 l  = unpack2(acc[gg][cc][0]);
          float2 hh = unpack2(acc[gg][cc][1]);
          float4 cand = make_float4(l.x+bv.x, l.y+bv.y, hh.x+bv.z, hh.y+bv.w);
          float ssv = sgs[gg][c];
          float nv  = 0.1f * snv[gg];
          float4 at = *(const float4*)&satt[gg][h4*4];
          float4 v  = *(float4*)&sc[gg][c][h4*4];
          v.x += ssv*(cand.x - v.x); v.x += nv*(at.x - v.x);
          v.y += ssv*(cand.y - v.y); v.y += nv*(at.y - v.y);
          v.z += ssv*(cand.z - v.z); v.z += nv*(at.z - v.z);
          v.w += ssv*(cand.w - v.w); v.w += nv*(at.w - v.w);
          *(float4*)&sc[gg][c][h4*4] = v;
        }
      }
    }
    __syncthreads(); // S9
    {
      #pragma unroll
      for (int pp = 0; pp < 2; pp++){
        int p = ht + pp*128;
        int ii = p >> 4, jj = p & 15;
        const float4* A  = (const float4*)sc[g][ii];
        const float4* Bv = (const float4*)sc[g][jj];
        float d0=0.f, d1=0.f, d2s=0.f, d3=0.f;
        #pragma unroll 8
        for (int k = 0; k < 32; k++){
          float4 a4 = A[k], b4 = Bv[k];
          d0 += a4.x*b4.x; d1 += a4.y*b4.y; d2s += a4.z*b4.z; d3 += a4.w*b4.w;
        }
        float dot = (d0+d1) + (d2s+d3);
        smix[g][ii][jj] = dot;
        if (ii == jj) ssq[g][ii] = dot;
      }
    }
    __syncthreads(); // S10
    {
      #pragma unroll
      for (int pass = 0; pass < 2; pass++){
        int row = pass*8 + wg*2 + (lane >> 4);
        int jj  = lane & 15;
        float Gij = smix[g][row][jj];
        float d2v = fmaxf(ssq[g][row] + ssq[g][jj] - 2.f*Gij, 0.f);
        float comp = -d2v / (ssp[g][row] + ssp[g][jj] + EPSF) + sma[g][jj];
        float mx = rmax16(comp);
        float ex = expf(comp - mx);
        float sm = rsum16(ex);
        float mix = ex / sm;
        smix[g][row][jj] = mix;
        float msp = rsum16(mix * ssp[g][jj]);
        float mms = rsum16(mix * sma[g][jj]);
        if ((lane & 15) == 0){ sms[g][row] = msp; smm[g][row] = mms; }
      }
    }
    __syncthreads(); // S11
    {
      float rl = srl[g];
      float cr[16];
      #pragma unroll
      for (int c = 0; c < 16; c++) cr[c] = sc[g][c][ht];
      #pragma unroll
      for (int i = 0; i < 16; i++){
        const float4* mr = (const float4*)smix[g][i];
        float4 m0 = mr[0], m1 = mr[1], m2v = mr[2], m3 = mr[3];
        float mc = m0.x*cr[0]+m0.y*cr[1]+m0.z*cr[2]+m0.w*cr[3]
                 + m1.x*cr[4]+m1.y*cr[5]+m1.z*cr[6]+m1.w*cr[7]
                 + m2v.x*cr[8]+m2v.y*cr[9]+m2v.z*cr[10]+m2v.w*cr[11]
                 + m3.x*cr[12]+m3.y*cr[13]+m3.z*cr[14]+m3.w*cr[15];
        sc[g][i][ht] = (1.f-rl)*cr[i] + rl*mc;
      }
      if (ht < 32){
        const bool ok = lane < 16;
        float rl2 = srl[g];
        float sp = ok ? ssp[g][lane] : 1.f;
        float m  = ok ? sma[g][lane] : 0.f;
        float sp2 = (1.f-rl2)*sp + rl2*(ok ? sms[g][lane] : 0.f);
        float m2  = (1.f-rl2)*m  + rl2*(ok ? smm[g][lane] : 0.f);
        float score = ok ? m2 + logf(1.f/(sp2+EPSF)+EPSF) : -3.4e38f;
        float mx = rmax16(score);
        float ex = ok ? expf(score - mx) : 0.f;
        float sm = rsum16(ex);
        float ca = ex / sm;
        if (ok){ ssp[g][lane] = sp2*(1.f - 0.05f*ca*valid) + EPSF; sma[g][lane] = m2; }
      }
    }
    __syncthreads(); // S12
  }

  // ---- epilogue ----
  if (ht < 32){
    const bool ok = lane < 16;
    float sp = ok ? ssp[g][lane] : 0.f;
    float m  = ok ? sma[g][lane] : 0.f;
    float score = ok ? m + logf(1.f/(sp+EPSF)+EPSF) : -3.4e38f;
    float mx = rmax16(score);
    float ex = ok ? expf(score - mx) : 0.f;
    float sm = rsum16(ex);
    float a  = ex / sm;
    if (ok) sal[g][lane] = a;
    float u   = rsum16(ok ? a*sp : 0.f);
    float ent = rsum16(ok ? -a*logf(fmaxf(a,1e-8f)) : 0.f);
    float mm2 = rmax16(ok ? m : -3.4e38f);
    float en  = mm2 + logf(rsum16(ok ? expf(m - mm2) : 0.f));
    float bv = ok ? a : -3.4e38f;
    int   bi = ok ? lane : 99;
    #pragma unroll
    for (int o = 8; o; o >>= 1){
      float ov = __shfl_xor_sync(0xffffffffu, bv, o);
      int   oi = __shfl_xor_sync(0xffffffffu, bi, o);
      if (ov > bv || (ov == bv && oi < bi)){ bv = ov; bi = oi; }
    }
    if (lane == 0){ sci[g][256] = u; sci[g][258] = en; sci[g][259] = ent; sidx[g] = bi; }
  }
  __syncthreads();
  {
    float core = 0.f;
    #pragma unroll
    for (int c = 0; c < 16; c++) core += sal[g][c] * sc[g][c][ht];
    float dv = 0.f;
    #pragma unroll
    for (int c = 0; c < 16; c++){ float dd = sc[g][c][ht] - core; dv += sal[g][c]*dd*dd; }
    dv = rsum32(dv);
    if (lane == 0) sred[g][wg][2] = dv;
    float strong = sc[g][sidx[g]][ht];
    sci[g][ht] = core;
    sci[g][128+ht] = strong;
  }
  __syncthreads();
  if (ht == 0) sci[g][257] = (sred[g][0][2]+sred[g][1][2]+sred[g][2][2]+sred[g][3][2]) * (1.f/128.f);
  __syncthreads();
  {
    u64 a0 = 0, a1 = 0;
    const int lo = isl * 65;
    #pragma unroll 4
    for (int i = lo; i < lo + 65; i++){
      u64 xp = pack2(sci[g][i]);
      ulonglong2 w = *(const ulonglong2*)&cw1[i*128 + j4*4];
      fma2(a0, xp, w.x); fma2(a1, xp, w.y);
    }
    float2 l = unpack2(a0), h2 = unpack2(a1);
    sbuf[g][isl][j4] = make_float4(l.x, l.y, h2.x, h2.y);
  }
  __syncthreads();
  {
    float s = cb1[ht];
    #pragma unroll
    for (int k = 0; k < 4; k++) s += ((const float*)sbuf[g][k])[ht];
    sh1[g][ht] = 0.5f * s * (1.f + erff(s * 0.70710678118654752440f));
  }
  __syncthreads();
  if (ht < 8){
    float s = cb2[ht];
    #pragma unroll 4
    for (int i = 0; i < 128; i++) s += sh1[g][i] * cw2[i*8 + ht];
    out[b*8 + ht] = s;
  }
}

extern "C" void kernel_launch(void* const* d_in, const int* in_sizes, int n_in,
                              void* d_out, int out_size){
  (void)in_sizes; (void)n_in; (void)out_size;
  cfrm_kernel<<<64, 256>>>(
    (const int*)  d_in[0],  (const float*)d_in[1],  (const float*)d_in[2],  (const float*)d_in[3],
    (const float*)d_in[4],  (const float*)d_in[5],  (const float*)d_in[6],  (const float*)d_in[7],
    (const float*)d_in[8],  (const float*)d_in[9],  (const float*)d_in[10], (const float*)d_in[11],
    (const float*)d_in[12], (const float*)d_in[13], (const float*)d_in[14], (const float*)d_in[15],
    (const float*)d_in[16], (const float*)d_in[17], (const float*)d_in[18], (const float*)d_in[19],
    (const float*)d_in[20], (const float*)d_in[21], (const float*)d_in[22], (const float*)d_in[23],
    (const float*)d_in[24], (const float*)d_in[25], (const float*)d_in[26], (const float*)d_in[27],
    (float*)d_out);
}

// round 4
// speedup vs baseline: 1.0763x; 1.0763x over previous
#include <cuda_runtime.h>
#include <math.h>

#define EPSF 1e-4f
typedef unsigned long long u64;

__device__ __forceinline__ u64 pack2(float x){
  u64 r; unsigned xi = __float_as_uint(x);
  asm("mov.b64 %0, {%1, %1};" : "=l"(r) : "r"(xi));
  return r;
}
__device__ __forceinline__ void fma2(u64 &acc, u64 a, u64 b){
  asm("fma.rn.f32x2 %0, %1, %2, %0;" : "+l"(acc) : "l"(a), "l"(b));
}
__device__ __forceinline__ float2 unpack2(u64 v){
  unsigned lo, hi;
  asm("mov.b64 {%0, %1}, %2;" : "=r"(lo), "=r"(hi) : "l"(v));
  return make_float2(__uint_as_float(lo), __uint_as_float(hi));
}
__device__ __forceinline__ float rsum32(float v){
  #pragma unroll
  for (int o=16;o;o>>=1) v += __shfl_xor_sync(0xffffffffu, v, o);
  return v;
}
__device__ __forceinline__ float rsum16(float v){
  #pragma unroll
  for (int o=8;o;o>>=1) v += __shfl_xor_sync(0xffffffffu, v, o);
  return v;
}
__device__ __forceinline__ float rmax16(float v){
  #pragma unroll
  for (int o=8;o;o>>=1) v = fmaxf(v, __shfl_xor_sync(0xffffffffu, v, o));
  return v;
}
__device__ __forceinline__ float sigm(float x){ return 1.f/(1.f+expf(-x)); }
__device__ __forceinline__ float splus(float x){ return fmaxf(x,0.f)+log1pf(expf(-fabsf(x))); }

struct Smem {
  float sc[4][16][132];
  float smix[4][16][16];
  float sci[4][260];
  float sct2[128][4];
  float sh1[4][128];
  float satt[4][128];
  float sbuf[4][4][128];   // [slice][group][j]
  float ssp[4][16], smaM[4][16], sal[4][16], sgs[4][16];
  float ssq[4][16], sms[4][16], smm[4][16];
  float sraw[4][4][16];
  float sred[4][4][3];
  float snv[4], srl[4];
  int sidx[4];
};

__global__ void __launch_bounds__(512,1) cfrm_kernel(
   const int* __restrict__ tokens, const float* __restrict__ emb,
   const float* __restrict__ ln_g, const float* __restrict__ ln_b,
   const float* __restrict__ w1, const float* __restrict__ b1,
   const float* __restrict__ w2, const float* __restrict__ b2,
   const float* __restrict__ gate_w, const float* __restrict__ gate_b,
   const float* __restrict__ assign_w, const float* __restrict__ assign_b,
   const float* __restrict__ nov_w, const float* __restrict__ nov_b,
   const float* __restrict__ relax_w, const float* __restrict__ relax_b,
   const float* __restrict__ cc_w, const float* __restrict__ cc_b,
   const float* __restrict__ cs_w, const float* __restrict__ cs_b,
   const float* __restrict__ md_w, const float* __restrict__ md_b,
   const float* __restrict__ att_w, const float* __restrict__ att_b,
   const float* __restrict__ cw1, const float* __restrict__ cb1,
   const float* __restrict__ cw2, const float* __restrict__ cb2,
   float* __restrict__ out)
{
  extern __shared__ __align__(16) char smem_raw[];
  Smem* S = (Smem*)smem_raw;

  const int tid  = threadIdx.x;
  const int g    = tid >> 7;      // group (batch within CTA)
  const int ht   = tid & 127;
  const int lane = tid & 31;
  const int wg   = (tid >> 5) & 3;
  const int b    = blockIdx.x * 4 + g;

  // shared-matvec mappings (whole CTA)
  const int jjm = tid & 127;      // output index for w1/w2/att
  const int sl4 = tid >> 7;       // reduction slice 0..3
  const int ccC = tid >> 5;       // cluster 0..15 for cc matvec
  const int ccH = tid & 31;       // float4 chunk of h for cc matvec

  for (int i = tid; i < 4*16*132; i += 512) ((float*)S->sc)[i] = 0.f;
  if (tid < 64){ ((float*)S->ssp)[tid] = 1.f; ((float*)S->smaM)[tid] = 0.f; }
  __syncthreads();

  for (int t = 0; t < 512; t++){
    const int tok = tokens[b*512 + t];
    const float valid = (tok != 0) ? 1.f : 0.f;
    const float e = emb[tok*128 + ht];
    {
      float ps = rsum32(e);
      float pq = rsum32(e*e);
      if (lane == 0){ S->sred[g][wg][0] = ps; S->sred[g][wg][1] = pq; }
    }
    if (ht < 32){
      const bool ok = lane < 16;
      float sp = ok ? S->ssp[g][lane] : 0.f;
      float m  = ok ? S->smaM[g][lane] : 0.f;
      float score = ok ? m + logf(1.f/(sp+EPSF)+EPSF) : -3.4e38f;
      float mx = rmax16(score);
      float ex = ok ? expf(score - mx) : 0.f;
      float sm = rsum16(ex);
      float a  = ex / sm;
      if (ok) S->sal[g][lane] = a;
      float u   = rsum16(ok ? a*sp : 0.f);
      float ent = rsum16(ok ? -a*logf(fmaxf(a,1e-8f)) : 0.f);
      float mm2 = rmax16(ok ? m : -3.4e38f);
      float en  = mm2 + logf(rsum16(ok ? expf(m - mm2) : 0.f));
      if (lane == 0){ S->sci[g][256] = u; S->sci[g][258] = en; S->sci[g][259] = ent; }
    }
    __syncthreads(); // S1
    {
      float mu = (S->sred[g][0][0]+S->sred[g][1][0]+S->sred[g][2][0]+S->sred[g][3][0]) * (1.f/128.f);
      float mq = (S->sred[g][0][1]+S->sred[g][1][1]+S->sred[g][2][1]+S->sred[g][3][1]) * (1.f/128.f);
      float var = mq - mu*mu;
      float te = (e - mu) * rsqrtf(var + 1e-5f) * ln_g[ht] + ln_b[ht];
      S->sci[g][ht] = te;
      float core = 0.f;
      #pragma unroll
      for (int c = 0; c < 16; c++) core += S->sal[g][c] * S->sc[g][c][ht];
      S->sci[g][128+ht] = core;
      float dv = 0.f;
      #pragma unroll
      for (int c = 0; c < 16; c++){ float dd = S->sc[g][c][ht] - core; dv += S->sal[g][c]*dd*dd; }
      dv = rsum32(dv);
      if (lane == 0) S->sred[g][wg][2] = dv;
    }
    __syncthreads(); // S2a
    if (ht == 0)
      S->sci[g][257] = (S->sred[g][0][2]+S->sred[g][1][2]+S->sred[g][2][2]+S->sred[g][3][2]) * (1.f/128.f);
    __syncthreads(); // S2b
    {
      // w1 [260,128], shared loads across 4 groups
      float a0=0.f, a1=0.f, a2=0.f, a3=0.f;
      const int lo = sl4 * 65;
      #pragma unroll 5
      for (int i = lo; i < lo + 65; i++){
        float w = w1[i*128 + jjm];
        a0 += S->sci[0][i]*w; a1 += S->sci[1][i]*w;
        a2 += S->sci[2][i]*w; a3 += S->sci[3][i]*w;
      }
      S->sbuf[sl4][0][jjm]=a0; S->sbuf[sl4][1][jjm]=a1;
      S->sbuf[sl4][2][jjm]=a2; S->sbuf[sl4][3][jjm]=a3;
    }
    __syncthreads(); // S3
    {
      float s = b1[ht] + S->sbuf[0][g][ht]+S->sbuf[1][g][ht]+S->sbuf[2][g][ht]+S->sbuf[3][g][ht];
      S->sh1[g][ht] = tanhf(s);
    }
    __syncthreads(); // S4
    {
      // w2 [128,128], shared
      float a0=0.f, a1=0.f, a2=0.f, a3=0.f;
      const int lo = sl4 * 32;
      #pragma unroll 8
      for (int i = lo; i < lo + 32; i++){
        float w = w2[i*128 + jjm];
        a0 += S->sh1[0][i]*w; a1 += S->sh1[1][i]*w;
        a2 += S->sh1[2][i]*w; a3 += S->sh1[3][i]*w;
      }
      S->sbuf[sl4][0][jjm]=a0; S->sbuf[sl4][1][jjm]=a1;
      S->sbuf[sl4][2][jjm]=a2; S->sbuf[sl4][3][jjm]=a3;
    }
    __syncthreads(); // S5
    {
      float s = b2[ht] + S->sbuf[0][g][ht]+S->sbuf[1][g][ht]+S->sbuf[2][g][ht]+S->sbuf[3][g][ht];
      S->sct2[ht][g] = tanhf(s);
    }
    __syncthreads(); // S6

    // ---- cc_w [128,2048]: one load feeds 4 groups; thread owns (cluster ccC, 4 h's)
    u64 accc[4][2];
    #pragma unroll
    for (int a=0;a<4;a++){ accc[a][0]=0; accc[a][1]=0; }
    {
      const ulonglong2* W = (const ulonglong2*)cc_w;
      const int base = ccC*32 + ccH;
      #pragma unroll 4
      for (int i = 0; i < 128; i++){
        float4 ct = *(const float4*)&S->sct2[i][0];
        ulonglong2 wv = W[i*512 + base];
        u64 p0 = pack2(ct.x), p1 = pack2(ct.y), p2 = pack2(ct.z), p3 = pack2(ct.w);
        fma2(accc[0][0], p0, wv.x); fma2(accc[0][1], p0, wv.y);
        fma2(accc[1][0], p1, wv.x); fma2(accc[1][1], p1, wv.y);
        fma2(accc[2][0], p2, wv.x); fma2(accc[2][1], p2, wv.y);
        fma2(accc[3][0], p3, wv.x); fma2(accc[3][1], p3, wv.y);
      }
    }
    {
      // att_w [128,128], shared
      float a0=0.f, a1=0.f, a2=0.f, a3=0.f;
      const int lo = sl4 * 32;
      #pragma unroll 8
      for (int i = lo; i < lo + 32; i++){
        float w = att_w[i*128 + jjm];
        a0 += S->sct2[i][0]*w; a1 += S->sct2[i][1]*w;
        a2 += S->sct2[i][2]*w; a3 += S->sct2[i][3]*w;
      }
      S->sbuf[sl4][0][jjm]=a0; S->sbuf[sl4][1][jjm]=a1;
      S->sbuf[sl4][2][jjm]=a2; S->sbuf[sl4][3][jjm]=a3;
    }
    if (ht < 64){
      const int head = ht >> 4;
      const int c = ht & 15;
      const float* W  = (head==0)? gate_w : (head==1)? assign_w : (head==2)? cs_w : md_w;
      const float* Bp = (head==0)? gate_b : (head==1)? assign_b : (head==2)? cs_b : md_b;
      float s = Bp[c];
      #pragma unroll 4
      for (int i = 0; i < 128; i++) s += S->sct2[i][g] * W[i*16 + c];
      S->sraw[g][head][c] = s;
    } else if (ht < 96){
      float s = 0.f;
      #pragma unroll
      for (int k = 0; k < 4; k++){ int i = (ht-64) + k*32; s += S->sct2[i][g] * nov_w[i]; }
      s = rsum32(s);
      if (lane == 0) S->snv[g] = sigm(s + nov_b[0]) * valid;
    } else {
      float s = 0.f;
      #pragma unroll
      for (int k = 0; k < 4; k++){ int i = (ht-96) + k*32; s += S->sct2[i][g] * relax_w[i]; }
      s = rsum32(s);
      if (lane == 0) S->srl[g] = sigm(s + relax_b[0]) * valid;
    }
    __syncthreads(); // S7
    {
      float s = att_b[ht] + S->sbuf[0][g][ht]+S->sbuf[1][g][ht]+S->sbuf[2][g][ht]+S->sbuf[3][g][ht];
      S->satt[g][ht] = s;
    }
    if (ht < 32){
      const bool ok = lane < 16;
      float graw = ok ? S->sraw[g][0][lane] : 0.f;
      float araw = ok ? S->sraw[g][1][lane] : -3.4e38f;
      float mx = rmax16(araw);
      float ex = ok ? expf(araw - mx) : 0.f;
      float sm = rsum16(ex);
      if (ok){
        float assign = ex / sm;
        float gate = sigm(graw) * valid;
        float ss = gate * assign;
        S->sgs[g][lane] = ss;
        float cs = splus(S->sraw[g][2][lane]) + EPSF;
        float md = tanhf(S->sraw[g][3][lane]);
        float sp = S->ssp[g][lane]; sp += ss*(cs - sp); S->ssp[g][lane] = sp;
        float m  = S->smaM[g][lane]; m += ss*md;        S->smaM[g][lane] = m;
      }
    }
    __syncthreads(); // S8
    {
      // center update: thread (ccC, ccH) for all 4 groups
      float4 bv = *(const float4*)&cc_b[ccC*128 + ccH*4];
      #pragma unroll
      for (int gg = 0; gg < 4; gg++){
        float2 l  = unpack2(accc[gg][0]);
        float2 hh = unpack2(accc[gg][1]);
        float4 cand = make_float4(l.x+bv.x, l.y+bv.y, hh.x+bv.z, hh.y+bv.w);
        float ssv = S->sgs[gg][ccC];
        float nv  = 0.1f * S->snv[gg];
        float4 at = *(const float4*)&S->satt[gg][ccH*4];
        float4 v  = *(float4*)&S->sc[gg][ccC][ccH*4];
        v.x += ssv*(cand.x - v.x); v.x += nv*(at.x - v.x);
        v.y += ssv*(cand.y - v.y); v.y += nv*(at.y - v.y);
        v.z += ssv*(cand.z - v.z); v.z += nv*(at.z - v.z);
        v.w += ssv*(cand.w - v.w); v.w += nv*(at.w - v.w);
        *(float4*)&S->sc[gg][ccC][ccH*4] = v;
      }
    }
    __syncthreads(); // S9
    {
      // Gram per group: 256 pairs, 2/thread; A reads broadcast, B dedup
      #pragma unroll
      for (int pp = 0; pp < 2; pp++){
        int p = ht + pp*128;
        int ii = p >> 4, jj = p & 15;
        const float4* A  = (const float4*)S->sc[g][ii];
        const float4* Bv = (const float4*)S->sc[g][jj];
        float d0=0.f, d1=0.f, d2s=0.f, d3=0.f;
        #pragma unroll 8
        for (int k = 0; k < 32; k++){
          float4 a4 = A[k], b4 = Bv[k];
          d0 += a4.x*b4.x; d1 += a4.y*b4.y; d2s += a4.z*b4.z; d3 += a4.w*b4.w;
        }
        float dot = (d0+d1) + (d2s+d3);
        S->smix[g][ii][jj] = dot;
        if (ii == jj) S->ssq[g][ii] = dot;
      }
    }
    __syncthreads(); // S10
    {
      #pragma unroll
      for (int pass = 0; pass < 2; pass++){
        int row = pass*8 + wg*2 + (lane >> 4);
        int jj  = lane & 15;
        float Gij = S->smix[g][row][jj];
        float d2v = fmaxf(S->ssq[g][row] + S->ssq[g][jj] - 2.f*Gij, 0.f);
        float comp = -d2v / (S->ssp[g][row] + S->ssp[g][jj] + EPSF) + S->smaM[g][jj];
        float mx = rmax16(comp);
        float ex = expf(comp - mx);
        float sm = rsum16(ex);
        float mix = ex / sm;
        S->smix[g][row][jj] = mix;
        float msp = rsum16(mix * S->ssp[g][jj]);
        float mms = rsum16(mix * S->smaM[g][jj]);
        if ((lane & 15) == 0){ S->sms[g][row] = msp; S->smm[g][row] = mms; }
      }
    }
    __syncthreads(); // S11
    {
      float rl = S->srl[g];
      float cr[16];
      #pragma unroll
      for (int c = 0; c < 16; c++) cr[c] = S->sc[g][c][ht];
      #pragma unroll
      for (int i = 0; i < 16; i++){
        const float4* mr = (const float4*)S->smix[g][i];
        float4 m0 = mr[0], m1 = mr[1], m2v = mr[2], m3 = mr[3];
        float mc = m0.x*cr[0]+m0.y*cr[1]+m0.z*cr[2]+m0.w*cr[3]
                 + m1.x*cr[4]+m1.y*cr[5]+m1.z*cr[6]+m1.w*cr[7]
                 + m2v.x*cr[8]+m2v.y*cr[9]+m2v.z*cr[10]+m2v.w*cr[11]
                 + m3.x*cr[12]+m3.y*cr[13]+m3.z*cr[14]+m3.w*cr[15];
        S->sc[g][i][ht] = (1.f-rl)*cr[i] + rl*mc;
      }
      if (ht < 32){
        const bool ok = lane < 16;
        float rl2 = S->srl[g];
        float sp = ok ? S->ssp[g][lane] : 1.f;
        float m  = ok ? S->smaM[g][lane] : 0.f;
        float sp2 = (1.f-rl2)*sp + rl2*(ok ? S->sms[g][lane] : 0.f);
        float m2  = (1.f-rl2)*m  + rl2*(ok ? S->smm[g][lane] : 0.f);
        float score = ok ? m2 + logf(1.f/(sp2+EPSF)+EPSF) : -3.4e38f;
        float mx = rmax16(score);
        float ex = ok ? expf(score - mx) : 0.f;
        float sm = rsum16(ex);
        float ca = ex / sm;
        if (ok){ S->ssp[g][lane] = sp2*(1.f - 0.05f*ca*valid) + EPSF; S->smaM[g][lane] = m2; }
      }
    }
    __syncthreads(); // S12
  }

  // ---- epilogue (per group) ----
  const int isl = ht >> 5;
  const int j4  = ht & 31;
  if (ht < 32){
    const bool ok = lane < 16;
    float sp = ok ? S->ssp[g][lane] : 0.f;
    float m  = ok ? S->smaM[g][lane] : 0.f;
    float score = ok ? m + logf(1.f/(sp+EPSF)+EPSF) : -3.4e38f;
    float mx = rmax16(score);
    float ex = ok ? expf(score - mx) : 0.f;
    float sm = rsum16(ex);
    float a  = ex / sm;
    if (ok) S->sal[g][lane] = a;
    float u   = rsum16(ok ? a*sp : 0.f);
    float ent = rsum16(ok ? -a*logf(fmaxf(a,1e-8f)) : 0.f);
    float mm2 = rmax16(ok ? m : -3.4e38f);
    float en  = mm2 + logf(rsum16(ok ? expf(m - mm2) : 0.f));
    float bv = ok ? a : -3.4e38f;
    int   bi = ok ? lane : 99;
    #pragma unroll
    for (int o = 8; o; o >>= 1){
      float ov = __shfl_xor_sync(0xffffffffu, bv, o);
      int   oi = __shfl_xor_sync(0xffffffffu, bi, o);
      if (ov > bv || (ov == bv && oi < bi)){ bv = ov; bi = oi; }
    }
    if (lane == 0){ S->sci[g][256] = u; S->sci[g][258] = en; S->sci[g][259] = ent; S->sidx[g] = bi; }
  }
  __syncthreads();
  {
    float core = 0.f;
    #pragma unroll
    for (int c = 0; c < 16; c++) core += S->sal[g][c] * S->sc[g][c][ht];
    float dv = 0.f;
    #pragma unroll
    for (int c = 0; c < 16; c++){ float dd = S->sc[g][c][ht] - core; dv += S->sal[g][c]*dd*dd; }
    dv = rsum32(dv);
    if (lane == 0) S->sred[g][wg][2] = dv;
    float strong = S->sc[g][S->sidx[g]][ht];
    S->sci[g][ht] = core;
    S->sci[g][128+ht] = strong;
  }
  __syncthreads();
  if (ht == 0)
    S->sci[g][257] = (S->sred[g][0][2]+S->sred[g][1][2]+S->sred[g][2][2]+S->sred[g][3][2]) * (1.f/128.f);
  __syncthreads();
  {
    u64 a0 = 0, a1 = 0;
    const int lo = isl * 65;
    #pragma unroll 4
    for (int i = lo; i < lo + 65; i++){
      u64 xp = pack2(S->sci[g][i]);
      ulonglong2 w = *(const ulonglong2*)&cw1[i*128 + j4*4];
      fma2(a0, xp, w.x); fma2(a1, xp, w.y);
    }
    float2 l = unpack2(a0), h2 = unpack2(a1);
    *(float4*)&S->sbuf[isl][g][j4*4] = make_float4(l.x, l.y, h2.x, h2.y);
  }
  __syncthreads();
  {
    float s = cb1[ht] + S->sbuf[0][g][ht]+S->sbuf[1][g][ht]+S->sbuf[2][g][ht]+S->sbuf[3][g][ht];
    S->sh1[g][ht] = 0.5f * s * (1.f + erff(s * 0.70710678118654752440f));
  }
  __syncthreads();
  if (ht < 8){
    float s = cb2[ht];
    #pragma unroll 4
    for (int i = 0; i < 128; i++) s += S->sh1[g][i] * cw2[i*8 + ht];
    out[b*8 + ht] = s;
  }
}

extern "C" void kernel_launch(void* const* d_in, const int* in_sizes, int n_in,
                              void* d_out, int out_size){
  (void)in_sizes; (void)n_in; (void)out_size;
  cudaFuncSetAttribute(cfrm_kernel, cudaFuncAttributeMaxDynamicSharedMemorySize, (int)sizeof(Smem));
  cfrm_kernel<<<32, 512, sizeof(Smem)>>>(
    (const int*)  d_in[0],  (const float*)d_in[1],  (const float*)d_in[2],  (const float*)d_in[3],
    (const float*)d_in[4],  (const float*)d_in[5],  (const float*)d_in[6],  (const float*)d_in[7],
    (const float*)d_in[8],  (const float*)d_in[9],  (const float*)d_in[10], (const float*)d_in[11],
    (const float*)d_in[12], (const float*)d_in[13], (const float*)d_in[14], (const float*)d_in[15],
    (const float*)d_in[16], (const float*)d_in[17], (const float*)d_in[18], (const float*)d_in[19],
    (const float*)d_in[20], (const float*)d_in[21], (const float*)d_in[22], (const float*)d_in[23],
    (const float*)d_in[24], (const float*)d_in[25], (const float*)d_in[26], (const float*)d_in[27],
    (float*)d_out);
}